// round 11
// baseline (speedup 1.0000x reference)
#include <cuda_runtime.h>
#include <stdint.h>
#include <limits.h>

// Problem constants (match reference)
#define HOP        160
#define FFT        1024
#define NUM_LABELS 72
#define BATCH      4
#define TLEN       240000
#define PAD        (FFT / 2)           // 512
#define LPAD       (TLEN + 2 * PAD)    // 241024
#define NOUT       ((LPAD - FFT) / HOP + 1)  // 1501

// Segment decomposition: window w = padded [160w, 160w+1024) = segments
// [5w, 5w+32) of 32 elements each.
#define SEGLEN        32
#define SEGS_PER_WIN  32
#define WINS_PER_CTA  32
#define SEGS_PER_CTA  187                  // 5*32 + 27
#define NCOLS         18                   // 72 bins packed 4-per-u32
#define WARPS         8
#define BLOCK         (WARPS * 32)
#define CTAS_X        47                   // ceil(1501/32)
#define CHUNKS        47                   // ceil(187/4): 4 segs (128 elem) per chunk
#define CPW           6                    // chunks per warp (ceil(47/8))
#define W_PER_WARP    4

__device__ __forceinline__ int reflect_idx(int j)   // j = padded index
{
    int o = j - PAD;
    if (o < 0) o = -o;
    else if (o >= TLEN) o = 2 * (TLEN - 1) - o;
    return o;
}

// Argmax over packed u16x2 accumulators (lane c<18 owns bins 4c..4c+3),
// lowest-label tie-break (matches jnp.argmax).
__device__ __forceinline__ void scan_write(uint32_t accE, uint32_t accO,
                                           int lane, float* __restrict__ orow,
                                           int w)
{
    int p = INT_MIN;
    if (lane < NCOLS) {
        int b0 = 4 * lane;
        p =         ((int)(accE & 0xFFFFu) << 7) | (127 - b0);
        p = max(p, ((int)(accO & 0xFFFFu) << 7) | (127 - (b0 + 1)));
        p = max(p, ((int)(accE >> 16)     << 7) | (127 - (b0 + 2)));
        p = max(p, ((int)(accO >> 16)     << 7) | (127 - (b0 + 3)));
    }
    p = __reduce_max_sync(0xFFFFFFFFu, p);
    if (lane == 0 && w < NOUT)
        orow[w] = (float)(127 - (p & 127));
}

__global__ void __launch_bounds__(BLOCK)
label_majority_seghist2(const int* __restrict__ lbl, float* __restrict__ out)
{
    // Column-major packed segment histograms sh[col*187 + seg]; pitch 187 is
    // odd -> phase-2 per-lane column reads are bank-conflict-free.
    __shared__ uint32_t sh[NCOLS * SEGS_PER_CTA];

    const int tid  = threadIdx.x;
    const int lane = tid & 31;
    const int wid  = tid >> 5;
    const int b    = blockIdx.y;
    const int bx   = blockIdx.x;
    const int w0   = bx * WINS_PER_CTA;

    const int* __restrict__ row  = lbl + (size_t)b * TLEN;
    float* __restrict__     orow = out + (size_t)b * NOUT;

    for (int i = tid; i < NCOLS * SEGS_PER_CTA; i += BLOCK)
        sh[i] = 0;
    __syncthreads();

    // ============ phase 1: per-segment packed histograms ===================
    // Each warp: 6 chunks of 128 elements. ALL loads issued first (MLP=6 int4
    // DRAM loads), then atomics drain. Per atomic step: 4 segments x random
    // cols -> low ATOMS conflict. Per-segment byte counts <= 32: no carry.
    const int cbase = wid * CPW;
    const bool interior = (bx > 0) && (bx < CTAS_X - 1);  // no reflect touched
    const int jbase = w0 * HOP;                 // padded index of segment 0

    int4 v[CPW];
    if (interior) {
        // unpadded offset of segment 0 = jbase - PAD; 16B-aligned (mult of 512)
        const int* __restrict__ p = row + (jbase - PAD);
        #pragma unroll
        for (int i = 0; i < CPW; i++) {
            int c = cbase + i;
            if (c < CHUNKS)
                v[i] = *(const int4*)(p + c * 128 + lane * 4);
        }
    } else {
        #pragma unroll
        for (int i = 0; i < CPW; i++) {
            int c = cbase + i;
            if (c < CHUNKS) {
                int j = jbase + c * 128 + lane * 4;
                v[i].x = row[reflect_idx(j)];
                v[i].y = row[reflect_idx(j + 1)];
                v[i].z = row[reflect_idx(j + 2)];
                v[i].w = row[reflect_idx(j + 3)];
            }
        }
    }
    #pragma unroll
    for (int i = 0; i < CPW; i++) {
        int c = cbase + i;
        if (c < CHUNKS) {
            int seg = c * 4 + (lane >> 3);      // this lane's segment
            if (seg < SEGS_PER_CTA) {           // chunk 46 tail guard
                atomicAdd(&sh[(v[i].x >> 2) * SEGS_PER_CTA + seg], 1u << ((v[i].x & 3) * 8));
                atomicAdd(&sh[(v[i].y >> 2) * SEGS_PER_CTA + seg], 1u << ((v[i].y & 3) * 8));
                atomicAdd(&sh[(v[i].z >> 2) * SEGS_PER_CTA + seg], 1u << ((v[i].z & 3) * 8));
                atomicAdd(&sh[(v[i].w >> 2) * SEGS_PER_CTA + seg], 1u << ((v[i].w & 3) * 8));
            }
        }
    }
    __syncthreads();

    // ============ phase 2: sliding window sums (no atomics) ================
    // Warp handles windows w0 + 4*wid + i. Lane c<18 owns bins 4c..4c+3,
    // u8x4 -> u16x2 accumulation (window sums <= 1024 fit u16).
    const int wrel0 = wid * W_PER_WARP;
    const uint32_t* __restrict__ col = sh + lane * SEGS_PER_CTA;
    const int srel0 = 5 * wrel0;

    uint32_t accE = 0, accO = 0;
    if (lane < NCOLS) {
        #pragma unroll
        for (int k = 0; k < SEGS_PER_WIN; k++) {
            uint32_t u = col[srel0 + k];
            accE += u & 0x00FF00FFu;
            accO += (u >> 8) & 0x00FF00FFu;
        }
    }
    scan_write(accE, accO, lane, orow, w0 + wrel0);

    #pragma unroll
    for (int i = 1; i < W_PER_WARP; i++) {
        if (lane < NCOLS) {
            const int so = srel0 + 5 * (i - 1);
            #pragma unroll
            for (int k = 0; k < 5; k++) {
                uint32_t uo = col[so + k];                  // leaving segs
                uint32_t un = col[so + SEGS_PER_WIN + k];   // entering segs
                accE += (un & 0x00FF00FFu)        - (uo & 0x00FF00FFu);
                accO += ((un >> 8) & 0x00FF00FFu) - ((uo >> 8) & 0x00FF00FFu);
            }
        }
        scan_write(accE, accO, lane, orow, w0 + wrel0 + i);
    }
}

extern "C" void kernel_launch(void* const* d_in, const int* in_sizes, int n_in,
                              void* d_out, int out_size)
{
    const int* lbl = (const int*)d_in[0];   // [B, T] int32
    // d_in[1]: all-ones conv weight — irrelevant (window sum == histogram).
    float* out = (float*)d_out;             // [B, NOUT], compared as float32

    dim3 grid(CTAS_X, BATCH);
    label_majority_seghist2<<<grid, BLOCK>>>(lbl, out);
}